// round 14
// baseline (speedup 1.0000x reference)
#include <cuda_runtime.h>

// Fixed shapes: I(16,3,512,512), T(16,256), P(3,16), Q(16,3)
#define BS        16
#define CHANS     3
#define HW        (512 * 512)          // 262144 floats per channel
#define NCH       (BS * CHANS)         // 48 channels
#define PARTS     16                   // blocks per channel
#define NBLOCKS   (NCH * PARTS)        // 768 blocks
#define THREADS   256
#define WARPS     (THREADS / 32)
#define NSLOTS    (NBLOCKS * WARPS)    // 6144 per-warp partials
#define KDIM      16

// Deterministic scratch: one fixed slot per warp, no atomics, no block reduce.
__device__ float g_partials[NSLOTS];

__device__ __forceinline__ void st_stream(float* p, float v) {
    asm volatile("st.global.cs.f32 [%0], %1;" :: "l"(p), "f"(v) : "memory");
}

__global__ __launch_bounds__(THREADS)
void dncm_reduce_kernel(const float* __restrict__ I) {
    const int bid  = blockIdx.x;          // 0 .. 767
    const int ch   = bid >> 4;            // / PARTS
    const int part = bid & (PARTS - 1);
    const int t    = threadIdx.x;

    const float4* __restrict__ base =
        reinterpret_cast<const float4*>(I + (size_t)ch * HW) + (size_t)part * (THREADS * 16);

    float s = 0.0f;
    // Two batches of 8 independent float4 loads (front-batched MLP=8)
    #pragma unroll
    for (int batch = 0; batch < 2; batch++) {
        float4 v[8];
        #pragma unroll
        for (int i = 0; i < 8; i++)
            v[i] = base[batch * (8 * THREADS) + i * THREADS + t];
        float b0 = 0.f, b1 = 0.f;
        #pragma unroll
        for (int i = 0; i < 8; i += 2) {
            b0 += (v[i].x + v[i].y) + (v[i].z + v[i].w);
            b1 += (v[i+1].x + v[i+1].y) + (v[i+1].z + v[i+1].w);
        }
        s += b0 + b1;
    }

    // Warp-level reduce only; lane 0 stores its own deterministic slot.
    #pragma unroll
    for (int off = 16; off > 0; off >>= 1)
        s += __shfl_xor_sync(0xffffffffu, s, off);

    if ((t & 31) == 0)
        st_stream(&g_partials[bid * WARPS + (t >> 5)], s);

    // No __syncthreads: CTA retires as soon as its warps store. Visibility for
    // the secondary is guaranteed by cudaGridDependencySynchronize (grid scope).
    if (t == 0)
        cudaTriggerProgrammaticLaunchCompletion();
}

// Epilogue (PDL secondary): prefetch T/Q/P before gridDepSync, then gather
// 6144 per-warp partials. 768 threads = 48 teams x 16 lanes; each lane loads
// 8 contiguous floats (2 x float4) of its channel's 128-float slot range.
__global__ __launch_bounds__(768)
void dncm_final_kernel(const float* __restrict__ T,
                       const float* __restrict__ P,
                       const float* __restrict__ Q,
                       float* __restrict__ out) {
    const int t  = threadIdx.x;        // 0..767
    const int ch = t >> 4;             // 0..47
    const int j  = t & 15;             // lane within team

    // ---- Prefetch phase (overlaps with primary tail) ----
    const int b = t >> 4;              // batch (valid for t < 256)
    const int k = t & 15;
    float4 t0, t1, t2, t3;
    float r[KDIM];
    float P0 = 0.f, P1 = 0.f, P2 = 0.f;
    if (t < 256) {
        const float4* __restrict__ Tv =
            reinterpret_cast<const float4*>(T + b * (KDIM * KDIM) + k * KDIM);
        t0 = Tv[0]; t1 = Tv[1]; t2 = Tv[2]; t3 = Tv[3];
        #pragma unroll
        for (int q = 0; q < KDIM; q++)
            r[q] = Q[q * 3 + 0] + Q[q * 3 + 1] + Q[q * 3 + 2];
        P0 = P[0 * KDIM + k];
        P1 = P[1 * KDIM + k];
        P2 = P[2 * KDIM + k];
    }

    cudaGridDependencySynchronize();

    // ---- Gather: channel ch owns slots [ch*128, ch*128+128) ----
    const float4* __restrict__ p4 =
        reinterpret_cast<const float4*>(g_partials + ch * (PARTS * WARPS)) + j * 2;
    float4 a = p4[0];
    float4 bq = p4[1];
    float s = ((a.x + a.y) + (a.z + a.w)) + ((bq.x + bq.y) + (bq.z + bq.w));

    #pragma unroll
    for (int off = 8; off > 0; off >>= 1)
        s += __shfl_xor_sync(0xffffffffu, s, off);

    __shared__ float S[NCH];
    if (j == 0) S[ch] = s;
    __syncthreads();

    if (t < 256) {
        // A[b,k] = sum_c S[b,c] * P[c,k]
        const float A = S[b * CHANS + 0] * P0
                      + S[b * CHANS + 1] * P1
                      + S[b * CHANS + 2] * P2;

        // d = T_b[k,:] . r
        float d = t0.x * r[0]  + t0.y * r[1]  + t0.z * r[2]  + t0.w * r[3]
                + t1.x * r[4]  + t1.y * r[5]  + t1.z * r[6]  + t1.w * r[7]
                + t2.x * r[8]  + t2.y * r[9]  + t2.z * r[10] + t2.w * r[11]
                + t3.x * r[12] + t3.y * r[13] + t3.z * r[14] + t3.w * r[15];

        float val = d * A;
        #pragma unroll
        for (int off = 8; off > 0; off >>= 1)
            val += __shfl_xor_sync(0xffffffffu, val, off);

        if (k == 0)
            out[b] = val * (1.0f / (float)(HW * CHANS));
    }
}

extern "C" void kernel_launch(void* const* d_in, const int* in_sizes, int n_in,
                              void* d_out, int out_size) {
    const float* I = (const float*)d_in[0];   // (16,3,512,512)
    const float* T = (const float*)d_in[1];   // (16,256)
    const float* P = (const float*)d_in[2];   // (3,16)
    const float* Q = (const float*)d_in[3];   // (16,3)
    float* out = (float*)d_out;               // (16,1)

    dncm_reduce_kernel<<<NBLOCKS, THREADS>>>(I);

    cudaLaunchConfig_t cfg = {};
    cfg.gridDim  = dim3(1, 1, 1);
    cfg.blockDim = dim3(768, 1, 1);
    cfg.dynamicSmemBytes = 0;
    cfg.stream = 0;
    cudaLaunchAttribute attr[1];
    attr[0].id = cudaLaunchAttributeProgrammaticStreamSerialization;
    attr[0].val.programmaticStreamSerializationAllowed = 1;
    cfg.attrs = attr;
    cfg.numAttrs = 1;
    cudaLaunchKernelEx(&cfg, dncm_final_kernel, T, P, Q, out);
}

// round 15
// speedup vs baseline: 1.0208x; 1.0208x over previous
#include <cuda_runtime.h>

// Fixed shapes: I(16,3,512,512), T(16,256), P(3,16), Q(16,3)
#define BS        16
#define CHANS     3
#define HW        (512 * 512)        // 262144 floats per channel
#define NCH       (BS * CHANS)       // 48 channel slabs
#define PARTS     16                 // partials per channel
#define NBLOCKS   (NCH * PARTS)      // 768 blocks
#define THREADS   256
#define KDIM      16
// Per block: 16384 floats = 2048 v8-groups; per thread: 8 x v8 (64 floats)

// Deterministic scratch: fixed write slots, no atomics.
__device__ float g_partials[NBLOCKS];

// 256-bit read-only load with L2 evict-last (sm_103a requires v8.b32 for this
// policy). Halves LDG issue count vs float4 and hints L2 retention.
__device__ __forceinline__ void ldg256_evict_last(const float* p, float* v) {
    unsigned int r0, r1, r2, r3, r4, r5, r6, r7;
    asm volatile("ld.global.nc.L2::evict_last.v8.b32 {%0,%1,%2,%3,%4,%5,%6,%7}, [%8];"
                 : "=r"(r0), "=r"(r1), "=r"(r2), "=r"(r3),
                   "=r"(r4), "=r"(r5), "=r"(r6), "=r"(r7)
                 : "l"(p));
    v[0] = __uint_as_float(r0); v[1] = __uint_as_float(r1);
    v[2] = __uint_as_float(r2); v[3] = __uint_as_float(r3);
    v[4] = __uint_as_float(r4); v[5] = __uint_as_float(r5);
    v[6] = __uint_as_float(r6); v[7] = __uint_as_float(r7);
}

__global__ __launch_bounds__(THREADS)
void dncm_reduce_kernel(const float* __restrict__ I) {
    const int bid  = blockIdx.x;          // 0 .. 767
    const int ch   = bid >> 4;            // / PARTS
    const int part = bid & (PARTS - 1);
    const int t    = threadIdx.x;

    const float* __restrict__ base =
        I + (size_t)ch * HW + (size_t)part * 16384;

    float s = 0.0f;
    // Two batches of 4 independent 32B loads (32 cache lines in flight/warp).
    #pragma unroll
    for (int batch = 0; batch < 2; batch++) {
        float v[4][8];
        #pragma unroll
        for (int i = 0; i < 4; i++) {
            const int g = batch * (4 * THREADS) + i * THREADS + t;  // v8-group id
            ldg256_evict_last(base + (size_t)g * 8, v[i]);
        }
        float b0 = 0.f, b1 = 0.f;
        #pragma unroll
        for (int i = 0; i < 4; i++) {
            b0 += ((v[i][0] + v[i][1]) + (v[i][2] + v[i][3]));
            b1 += ((v[i][4] + v[i][5]) + (v[i][6] + v[i][7]));
        }
        s += b0 + b1;
    }

    #pragma unroll
    for (int off = 16; off > 0; off >>= 1)
        s += __shfl_xor_sync(0xffffffffu, s, off);

    __shared__ float smem[THREADS / 32];
    if ((t & 31) == 0) smem[t >> 5] = s;
    __syncthreads();

    if (t == 0) {
        float tot = 0.0f;
        #pragma unroll
        for (int i = 0; i < THREADS / 32; i++) tot += smem[i];
        g_partials[bid] = tot;   // fixed slot -> deterministic

        cudaTriggerProgrammaticLaunchCompletion();
    }
}

// Epilogue (PDL secondary): prefetch T/Q/P before gridDepSync, then consume
// the 768 partials. 768 threads = 48 teams x 16 lanes.
__global__ __launch_bounds__(768)
void dncm_final_kernel(const float* __restrict__ T,
                       const float* __restrict__ P,
                       const float* __restrict__ Q,
                       float* __restrict__ out) {
    const int t  = threadIdx.x;        // 0..767
    const int ch = t >> 4;             // 0..47
    const int j  = t & 15;             // lane within team

    // ---- Prefetch phase (overlaps with primary tail) ----
    const int b = t >> 4;              // batch (valid for t < 256)
    const int k = t & 15;              // k index
    float4 t0, t1, t2, t3;
    float r[KDIM];
    float P0 = 0.f, P1 = 0.f, P2 = 0.f;
    if (t < 256) {
        const float4* __restrict__ Tv =
            reinterpret_cast<const float4*>(T + b * (KDIM * KDIM) + k * KDIM);
        t0 = Tv[0]; t1 = Tv[1]; t2 = Tv[2]; t3 = Tv[3];
        #pragma unroll
        for (int q = 0; q < KDIM; q++)
            r[q] = Q[q * 3 + 0] + Q[q * 3 + 1] + Q[q * 3 + 2];
        P0 = P[0 * KDIM + k];
        P1 = P[1 * KDIM + k];
        P2 = P[2 * KDIM + k];
    }

    // ---- Wait for the primary grid's memory to be visible ----
    cudaGridDependencySynchronize();

    // ---- Reduce partials: 16 lanes per channel, 1 load each ----
    float s = g_partials[ch * PARTS + j];
    #pragma unroll
    for (int off = 8; off > 0; off >>= 1)
        s += __shfl_xor_sync(0xffffffffu, s, off);

    __shared__ float S[NCH];
    if (j == 0) S[ch] = s;
    __syncthreads();

    if (t < 256) {
        // A[b,k] = sum_c S[b,c] * P[c,k]
        const float A = S[b * CHANS + 0] * P0
                      + S[b * CHANS + 1] * P1
                      + S[b * CHANS + 2] * P2;

        // d = T_b[k,:] . r
        float d = t0.x * r[0]  + t0.y * r[1]  + t0.z * r[2]  + t0.w * r[3]
                + t1.x * r[4]  + t1.y * r[5]  + t1.z * r[6]  + t1.w * r[7]
                + t2.x * r[8]  + t2.y * r[9]  + t2.z * r[10] + t2.w * r[11]
                + t3.x * r[12] + t3.y * r[13] + t3.z * r[14] + t3.w * r[15];

        float val = d * A;
        #pragma unroll
        for (int off = 8; off > 0; off >>= 1)
            val += __shfl_xor_sync(0xffffffffu, val, off);

        if (k == 0)
            out[b] = val * (1.0f / (float)(HW * CHANS));
    }
}

extern "C" void kernel_launch(void* const* d_in, const int* in_sizes, int n_in,
                              void* d_out, int out_size) {
    const float* I = (const float*)d_in[0];   // (16,3,512,512)
    const float* T = (const float*)d_in[1];   // (16,256)
    const float* P = (const float*)d_in[2];   // (3,16)
    const float* Q = (const float*)d_in[3];   // (16,3)
    float* out = (float*)d_out;               // (16,1)

    dncm_reduce_kernel<<<NBLOCKS, THREADS>>>(I);

    cudaLaunchConfig_t cfg = {};
    cfg.gridDim  = dim3(1, 1, 1);
    cfg.blockDim = dim3(768, 1, 1);
    cfg.dynamicSmemBytes = 0;
    cfg.stream = 0;
    cudaLaunchAttribute attr[1];
    attr[0].id = cudaLaunchAttributeProgrammaticStreamSerialization;
    attr[0].val.programmaticStreamSerializationAllowed = 1;
    cfg.attrs = attr;
    cfg.numAttrs = 1;
    cudaLaunchKernelEx(&cfg, dncm_final_kernel, T, P, Q, out);
}

// round 16
// speedup vs baseline: 1.2657x; 1.2399x over previous
#include <cuda_runtime.h>

// Fixed shapes: I(16,3,512,512), T(16,256), P(3,16), Q(16,3)
#define BS        16
#define CHANS     3
#define HW        (512 * 512)        // 262144 floats per channel
#define NCH       (BS * CHANS)       // 48 channel slabs
#define PARTS     16                 // partials per channel
#define NBLOCKS   (NCH * PARTS)      // 768 blocks
#define THREADS   256
#define KDIM      16
// Per block: 16384 floats = 2048 v8-groups; per thread: 8 x v8 (64 floats)

// Deterministic scratch: fixed write slots, no atomics.
__device__ float g_partials[NBLOCKS];

// 256-bit read-only load with L2 evict-last (sm_103a requires v8.b32 for this
// policy). Halves LDG issue count vs float4 and hints L2 retention.
__device__ __forceinline__ void ldg256_evict_last(const float* p, float* v) {
    unsigned int r0, r1, r2, r3, r4, r5, r6, r7;
    asm volatile("ld.global.nc.L2::evict_last.v8.b32 {%0,%1,%2,%3,%4,%5,%6,%7}, [%8];"
                 : "=r"(r0), "=r"(r1), "=r"(r2), "=r"(r3),
                   "=r"(r4), "=r"(r5), "=r"(r6), "=r"(r7)
                 : "l"(p));
    v[0] = __uint_as_float(r0); v[1] = __uint_as_float(r1);
    v[2] = __uint_as_float(r2); v[3] = __uint_as_float(r3);
    v[4] = __uint_as_float(r4); v[5] = __uint_as_float(r5);
    v[6] = __uint_as_float(r6); v[7] = __uint_as_float(r7);
}

__global__ __launch_bounds__(THREADS)
void dncm_reduce_kernel(const float* __restrict__ I) {
    const int bid  = blockIdx.x;          // 0 .. 767
    const int ch   = bid >> 4;            // / PARTS
    const int part = bid & (PARTS - 1);
    const int t    = threadIdx.x;

    // EARLY PDL trigger: all 768 CTAs are in wave 1, so the dependent kernel
    // launches almost immediately and its ramp + T/Q/P prefetch fully overlap
    // the DRAM stream below. Correctness: the secondary's
    // cudaGridDependencySynchronize still waits for this WHOLE grid to finish.
    if (t == 0)
        cudaTriggerProgrammaticLaunchCompletion();

    const float* __restrict__ base =
        I + (size_t)ch * HW + (size_t)part * 16384;

    float s = 0.0f;
    // Two batches of 4 independent 32B loads (32 cache lines in flight/warp).
    #pragma unroll
    for (int batch = 0; batch < 2; batch++) {
        float v[4][8];
        #pragma unroll
        for (int i = 0; i < 4; i++) {
            const int g = batch * (4 * THREADS) + i * THREADS + t;  // v8-group id
            ldg256_evict_last(base + (size_t)g * 8, v[i]);
        }
        float b0 = 0.f, b1 = 0.f;
        #pragma unroll
        for (int i = 0; i < 4; i++) {
            b0 += ((v[i][0] + v[i][1]) + (v[i][2] + v[i][3]));
            b1 += ((v[i][4] + v[i][5]) + (v[i][6] + v[i][7]));
        }
        s += b0 + b1;
    }

    #pragma unroll
    for (int off = 16; off > 0; off >>= 1)
        s += __shfl_xor_sync(0xffffffffu, s, off);

    __shared__ float smem[THREADS / 32];
    if ((t & 31) == 0) smem[t >> 5] = s;
    __syncthreads();

    if (t == 0) {
        float tot = 0.0f;
        #pragma unroll
        for (int i = 0; i < THREADS / 32; i++) tot += smem[i];
        g_partials[bid] = tot;   // fixed slot -> deterministic
    }
}

// Epilogue (PDL secondary): prefetch T/Q/P before gridDepSync, then consume
// the 768 partials. 768 threads = 48 teams x 16 lanes.
__global__ __launch_bounds__(768)
void dncm_final_kernel(const float* __restrict__ T,
                       const float* __restrict__ P,
                       const float* __restrict__ Q,
                       float* __restrict__ out) {
    const int t  = threadIdx.x;        // 0..767
    const int ch = t >> 4;             // 0..47
    const int j  = t & 15;             // lane within team

    // ---- Prefetch phase (overlaps with the primary's DRAM stream) ----
    const int b = t >> 4;              // batch (valid for t < 256)
    const int k = t & 15;              // k index
    float4 t0, t1, t2, t3;
    float r[KDIM];
    float P0 = 0.f, P1 = 0.f, P2 = 0.f;
    if (t < 256) {
        const float4* __restrict__ Tv =
            reinterpret_cast<const float4*>(T + b * (KDIM * KDIM) + k * KDIM);
        t0 = Tv[0]; t1 = Tv[1]; t2 = Tv[2]; t3 = Tv[3];
        #pragma unroll
        for (int q = 0; q < KDIM; q++)
            r[q] = Q[q * 3 + 0] + Q[q * 3 + 1] + Q[q * 3 + 2];
        P0 = P[0 * KDIM + k];
        P1 = P[1 * KDIM + k];
        P2 = P[2 * KDIM + k];
    }

    // ---- Wait for the primary grid to fully complete (memory visible) ----
    cudaGridDependencySynchronize();

    // ---- Reduce partials: 16 lanes per channel, 1 load each ----
    float s = g_partials[ch * PARTS + j];
    #pragma unroll
    for (int off = 8; off > 0; off >>= 1)
        s += __shfl_xor_sync(0xffffffffu, s, off);

    __shared__ float S[NCH];
    if (j == 0) S[ch] = s;
    __syncthreads();

    if (t < 256) {
        // A[b,k] = sum_c S[b,c] * P[c,k]
        const float A = S[b * CHANS + 0] * P0
                      + S[b * CHANS + 1] * P1
                      + S[b * CHANS + 2] * P2;

        // d = T_b[k,:] . r
        float d = t0.x * r[0]  + t0.y * r[1]  + t0.z * r[2]  + t0.w * r[3]
                + t1.x * r[4]  + t1.y * r[5]  + t1.z * r[6]  + t1.w * r[7]
                + t2.x * r[8]  + t2.y * r[9]  + t2.z * r[10] + t2.w * r[11]
                + t3.x * r[12] + t3.y * r[13] + t3.z * r[14] + t3.w * r[15];

        float val = d * A;
        #pragma unroll
        for (int off = 8; off > 0; off >>= 1)
            val += __shfl_xor_sync(0xffffffffu, val, off);

        if (k == 0)
            out[b] = val * (1.0f / (float)(HW * CHANS));
    }
}

extern "C" void kernel_launch(void* const* d_in, const int* in_sizes, int n_in,
                              void* d_out, int out_size) {
    const float* I = (const float*)d_in[0];   // (16,3,512,512)
    const float* T = (const float*)d_in[1];   // (16,256)
    const float* P = (const float*)d_in[2];   // (3,16)
    const float* Q = (const float*)d_in[3];   // (16,3)
    float* out = (float*)d_out;               // (16,1)

    dncm_reduce_kernel<<<NBLOCKS, THREADS>>>(I);

    cudaLaunchConfig_t cfg = {};
    cfg.gridDim  = dim3(1, 1, 1);
    cfg.blockDim = dim3(768, 1, 1);
    cfg.dynamicSmemBytes = 0;
    cfg.stream = 0;
    cudaLaunchAttribute attr[1];
    attr[0].id = cudaLaunchAttributeProgrammaticStreamSerialization;
    attr[0].val.programmaticStreamSerializationAllowed = 1;
    cfg.attrs = attr;
    cfg.numAttrs = 1;
    cudaLaunchKernelEx(&cfg, dncm_final_kernel, T, P, Q, out);
}